// round 1
// baseline (speedup 1.0000x reference)
#include <cuda_runtime.h>
#include <cstddef>

#define BB   8
#define NF   64
#define FIN  192
#define FH   128
#define LATD 512
#define PT   61824
#define P0   16384   // 128*128

// ---------------- scratch (device globals; no allocation) ----------------
__device__ float g_out [BB*NF *P0];
__device__ float g_perc[BB*FIN*P0];
__device__ float g_h1  [BB*FH *P0];
__device__ float g_h2  [BB*FH *P0];
__device__ float g_full[BB*NF *P0];
__device__ float g_dyn [BB*PT];
__device__ float g_wAT [BB*FIN*FH];   // [192][128] per sample (w_in^T)
__device__ float g_wMT [BB*FH*FH];    // [128][128] per sample (w_mid^T)
__device__ float g_wCDT[BB*320*NF];   // [320][64]: rows 0..127 w_out^T, 128..319 w_sk^T
__device__ float g_bA  [BB*FH];
__device__ float g_bM  [BB*FH];
__device__ float g_bCD [BB*NF];
__device__ float g_hvec[BB*NF];

__device__ __forceinline__ float lrelu(float x){ return x > 0.0f ? x : 0.2f*x; }

// ---------------- input conv1x1 + res_block, writes emb0 ----------------
// blockDim = 64 (thread = output channel), each block does 64 pixels of one sample.
__global__ void k_input(const float* __restrict__ x, const float* __restrict__ in_w,
                        const float* __restrict__ in_b,
                        const float* __restrict__ w0, const float* __restrict__ b0,
                        const float* __restrict__ w1, const float* __restrict__ b1,
                        float* __restrict__ emb0)
{
    __shared__ float s_w0[NF*NF];   // swizzled: [o][ (i+o)&63 ]
    __shared__ float s_w1[NF*NF];
    __shared__ float s_a [NF*4];    // [i][py]
    const int o = threadIdx.x;
    const int b = blockIdx.y;
    const int pbase = blockIdx.x * 64;
    for (int e = o; e < NF*NF; e += 64) {
        int r = e >> 6, i = e & 63;
        s_w0[(r<<6) | ((i + r) & 63)] = w0[e];
        s_w1[(r<<6) | ((i + r) & 63)] = w1[e];
    }
    const float iw0 = in_w[o*3+0], iw1 = in_w[o*3+1], iw2 = in_w[o*3+2];
    const float bin = in_b[o], bb0 = b0[o], bb1 = b1[o];
    __syncthreads();
    for (int it = 0; it < 16; ++it) {
        const int p4 = pbase + it*4;
        float v[4];
        #pragma unroll
        for (int py = 0; py < 4; ++py) {
            int p = p4 + py;
            v[py] = bin + iw0*x[(b*3+0)*P0+p] + iw1*x[(b*3+1)*P0+p] + iw2*x[(b*3+2)*P0+p];
        }
        __syncthreads();  // previous iteration's reads of s_a done
        *(float4*)&s_a[o*4] = make_float4(lrelu(v[0]),lrelu(v[1]),lrelu(v[2]),lrelu(v[3]));
        __syncthreads();
        float t[4] = {bb0,bb0,bb0,bb0};
        #pragma unroll
        for (int i = 0; i < NF; ++i) {
            float w = s_w0[(o<<6) | ((i + o) & 63)];
            float4 a = *(const float4*)&s_a[i*4];
            t[0] += w*a.x; t[1] += w*a.y; t[2] += w*a.z; t[3] += w*a.w;
        }
        __syncthreads();
        *(float4*)&s_a[o*4] = make_float4(lrelu(t[0]),lrelu(t[1]),lrelu(t[2]),lrelu(t[3]));
        __syncthreads();
        float u[4] = {bb1,bb1,bb1,bb1};
        #pragma unroll
        for (int i = 0; i < NF; ++i) {
            float w = s_w1[(o<<6) | ((i + o) & 63)];
            float4 a = *(const float4*)&s_a[i*4];
            u[0] += w*a.x; u[1] += w*a.y; u[2] += w*a.z; u[3] += w*a.w;
        }
        #pragma unroll
        for (int py = 0; py < 4; ++py) {
            float r = v[py] + 0.1f*u[py];
            size_t idx = (size_t)(b*NF+o)*P0 + p4 + py;
            g_out[idx] = r;
            emb0[idx]  = r;
        }
    }
}

// ---------------- hypernet: dyn = inj_lat @ hyp_w + hyp_b ----------------
__global__ void k_hyper(const float* __restrict__ inj, const float* __restrict__ hw,
                        const float* __restrict__ hb)
{
    __shared__ float s_inj[BB*LATD];
    const int tid = threadIdx.x;  // 128
    for (int e = tid; e < BB*LATD; e += 128) s_inj[e] = inj[e];
    __syncthreads();
    const int j = blockIdx.x*128 + tid;
    if (j >= PT) return;
    float acc[BB];
    #pragma unroll
    for (int b = 0; b < BB; ++b) acc[b] = 0.f;
    for (int k = 0; k < LATD; ++k) {
        float w = hw[(size_t)k*PT + j];
        #pragma unroll
        for (int b = 0; b < BB; ++b) acc[b] += s_inj[b*LATD+k]*w;
    }
    const float bb = hb[j];
    #pragma unroll
    for (int b = 0; b < BB; ++b) g_dyn[(size_t)b*PT + j] = acc[b] + bb;
}

// ---------------- transpose dyn params into GEMM-friendly layout ----------------
__global__ void k_tr()
{
    const int b = blockIdx.y;
    int i = blockIdx.x*256 + threadIdx.x;
    const float* d = g_dyn + (size_t)b*PT;
    if (i < FIN*FH) { int k = i/FH, o = i%FH; g_wAT[(size_t)b*FIN*FH + i] = d[o*FIN + k]; return; }
    i -= FIN*FH;
    if (i < FH*FH)  { int k = i/FH, o = i%FH; g_wMT[(size_t)b*FH*FH + i] = d[24704 + o*FH + k]; return; }
    i -= FH*FH;
    if (i < 320*NF) { int k = i/NF, o = i%NF;
        g_wCDT[(size_t)b*320*NF + i] = (k < FH) ? d[41216 + o*FH + k]
                                                : d[49472 + o*FIN + (k-FH)];
        return; }
    i -= 320*NF;
    if (i < FH) { g_bA[b*FH+i] = d[24576+i]; return; }
    i -= FH;
    if (i < FH) { g_bM[b*FH+i] = d[41088+i]; return; }
    i -= FH;
    if (i < NF) { g_bCD[b*NF+i] = d[49408+i] + d[61760+i]; return; }
}

// ---------------- sin_sobel: g_out -> g_perc (id | dx | dy), zero pad ----------------
__global__ void k_sobel(int H)
{
    const int P = H*H;
    const int idx = blockIdx.x*256 + threadIdx.x;
    const int total = BB*NF*P;
    if (idx >= total) return;
    const int p = idx % P;
    const int c = (idx / P) % NF;
    const int b = idx / (P*NF);
    const int y = p / H, xx = p % H;
    const float* src = g_out + (size_t)(b*NF + c)*P;
    float c00 = src[p];
    float m00 = (y>0   && xx>0  ) ? src[(y-1)*H+xx-1] : 0.f;
    float m01 = (y>0            ) ? src[(y-1)*H+xx  ] : 0.f;
    float m02 = (y>0   && xx<H-1) ? src[(y-1)*H+xx+1] : 0.f;
    float m10 = (         xx>0  ) ? src[ y   *H+xx-1] : 0.f;
    float m12 = (         xx<H-1) ? src[ y   *H+xx+1] : 0.f;
    float m20 = (y<H-1 && xx>0  ) ? src[(y+1)*H+xx-1] : 0.f;
    float m21 = (y<H-1          ) ? src[(y+1)*H+xx  ] : 0.f;
    float m22 = (y<H-1 && xx<H-1) ? src[(y+1)*H+xx+1] : 0.f;
    float sx = (m00 - m02 + 2.f*(m10 - m12) + m20 - m22) * 0.125f;
    float sy = (m00 + 2.f*m01 + m02 - m20 - 2.f*m21 - m22) * 0.125f;
    float* dst = g_perc + (size_t)b*FIN*P;
    dst[(size_t) c      *P + p] = c00;
    dst[(size_t)(NF+c)  *P + p] = sx;
    dst[(size_t)(2*NF+c)*P + p] = sy;
}

// ---------------- per-sample SGEMM: C[n][p] = sum_k A[k][p] * Wt[k][n] (+epilogue) ----
// EPI 0: C = lrelu(v + bias)          EPI 1: C = O + leak * (v + bias)
template<int EPI>
__global__ void __launch_bounds__(256) k_gemm(
    const float* __restrict__ A1, int K1, long long sA1,
    const float* __restrict__ A2, int K2, long long sA2,
    const float* __restrict__ Wt, int ldw, long long sW,
    const float* __restrict__ bias, int sBias,
    float* __restrict__ C, long long sC,
    const float* __restrict__ O, const float* __restrict__ leak_ptr,
    int P, int tilesM)
{
    const int BM = 128, BN = 64, BK = 16;
    const int b = blockIdx.y;
    const int tileM = blockIdx.x % tilesM;
    const int n0 = (blockIdx.x / tilesM) * BN;
    const int m0 = tileM * BM;
    A1 += (size_t)b * sA1;
    if (A2) A2 += (size_t)b * sA2;
    Wt   += (size_t)b * sW;
    bias += (size_t)b * sBias;
    C    += (size_t)b * sC;

    __shared__ float As[BK][BM];
    __shared__ float Ws[BK][BN];
    const int tid = threadIdx.x;
    const int tm = tid & 15, tn = tid >> 4;
    float acc[4][8];
    #pragma unroll
    for (int j = 0; j < 4; ++j)
        #pragma unroll
        for (int i = 0; i < 8; ++i) acc[j][i] = 0.f;

    const int K = K1 + K2;
    for (int k0 = 0; k0 < K; k0 += BK) {
        #pragma unroll
        for (int l = 0; l < 2; ++l) {
            int f  = tid + l*256;            // 512 float4 loads for As
            int kc = f >> 5;
            int mv = (f & 31) << 2;
            int kk = k0 + kc;
            const float* src = (kk < K1) ? (A1 + (size_t)kk*P) : (A2 + (size_t)(kk-K1)*P);
            int m = m0 + mv;
            float4 v;
            if (m + 4 <= P) v = *(const float4*)(src + m);
            else {
                v.x = (m   < P) ? src[m  ] : 0.f;
                v.y = (m+1 < P) ? src[m+1] : 0.f;
                v.z = (m+2 < P) ? src[m+2] : 0.f;
                v.w = 0.f;
            }
            *(float4*)&As[kc][mv] = v;
        }
        {
            int kc = tid >> 4, nv = (tid & 15) << 2;  // 256 float4 for Ws
            *(float4*)&Ws[kc][nv] = *(const float4*)(Wt + (size_t)(k0+kc)*ldw + n0 + nv);
        }
        __syncthreads();
        #pragma unroll
        for (int kc = 0; kc < BK; ++kc) {
            float4 a0 = *(const float4*)&As[kc][tm*8];
            float4 a1 = *(const float4*)&As[kc][tm*8+4];
            float4 w  = *(const float4*)&Ws[kc][tn*4];
            float am[8] = {a0.x,a0.y,a0.z,a0.w,a1.x,a1.y,a1.z,a1.w};
            float wn[4] = {w.x,w.y,w.z,w.w};
            #pragma unroll
            for (int j = 0; j < 4; ++j)
                #pragma unroll
                for (int i = 0; i < 8; ++i)
                    acc[j][i] += wn[j]*am[i];
        }
        __syncthreads();
    }

    float lk = 0.f;
    if (EPI == 1) { lk = *leak_ptr; lk = fminf(fmaxf(lk, 0.001f), 1000.f); }
    #pragma unroll
    for (int j = 0; j < 4; ++j) {
        const int n = n0 + tn*4 + j;
        const float bv = bias[n];
        #pragma unroll
        for (int i = 0; i < 8; ++i) {
            const int m = m0 + tm*8 + i;
            if (m < P) {
                float v = acc[j][i] + bv;
                size_t off = (size_t)n*P + m;
                if (EPI == 0) C[off] = lrelu(v);
                else          C[off] = O[(size_t)b*sC + off] + lk*v;
            }
        }
    }
}

// ---------------- gauss 3x3 (zero pad) + 2x2 mean, writes g_out + emb ----------------
__global__ void k_down(int H, float* __restrict__ emb)
{
    const int Hn = H >> 1, Pn = Hn*Hn;
    const int idx = blockIdx.x*256 + threadIdx.x;
    if (idx >= BB*NF*Pn) return;
    const int p = idx % Pn;
    const int c = (idx / Pn) % NF;
    const int b = idx / (Pn*NF);
    const int oy = p / Hn, ox = p % Hn;
    const float* src = g_full + (size_t)(b*NF+c)*H*H;
    const float G0 = 0.27406861906119695f;   // exp(-.5)/(1+2exp(-.5))
    const float G1 = 0.72593138093880305f;   // G0 + 1/(1+2exp(-.5))
    const float u4[4] = {G0, G1, G1, G0};
    float acc = 0.f;
    #pragma unroll
    for (int r = 0; r < 4; ++r) {
        int yy = 2*oy + r - 1;
        if (yy < 0 || yy >= H) continue;
        float rowacc = 0.f;
        #pragma unroll
        for (int cc = 0; cc < 4; ++cc) {
            int xx = 2*ox + cc - 1;
            if (xx < 0 || xx >= H) continue;
            rowacc += u4[cc]*src[yy*H+xx];
        }
        acc += u4[r]*rowacc;
    }
    acc *= 0.25f;
    const size_t o = (size_t)(b*NF+c)*Pn + p;
    g_out[o] = acc;
    emb[o]   = acc;
}

// ---------------- tail res_block at 2x2 + spatial mean -> g_hvec ----------------
__global__ void k_tail(const float* __restrict__ w0, const float* __restrict__ b0,
                       const float* __restrict__ w1, const float* __restrict__ b1)
{
    __shared__ float s_w0[NF*NF], s_w1[NF*NF], s_a[NF*4];
    const int o = threadIdx.x, b = blockIdx.x;
    for (int e = o; e < NF*NF; e += 64) {
        int r = e >> 6, i = e & 63;
        s_w0[(r<<6) | ((i + r) & 63)] = w0[e];
        s_w1[(r<<6) | ((i + r) & 63)] = w1[e];
    }
    const float bb0 = b0[o], bb1 = b1[o];
    __syncthreads();
    float v[4];
    #pragma unroll
    for (int py = 0; py < 4; ++py) v[py] = g_out[(size_t)(b*NF+o)*4 + py];
    *(float4*)&s_a[o*4] = make_float4(lrelu(v[0]),lrelu(v[1]),lrelu(v[2]),lrelu(v[3]));
    __syncthreads();
    float t[4] = {bb0,bb0,bb0,bb0};
    #pragma unroll
    for (int i = 0; i < NF; ++i) {
        float w = s_w0[(o<<6) | ((i + o) & 63)];
        float4 a = *(const float4*)&s_a[i*4];
        t[0] += w*a.x; t[1] += w*a.y; t[2] += w*a.z; t[3] += w*a.w;
    }
    __syncthreads();
    *(float4*)&s_a[o*4] = make_float4(lrelu(t[0]),lrelu(t[1]),lrelu(t[2]),lrelu(t[3]));
    __syncthreads();
    float u[4] = {bb1,bb1,bb1,bb1};
    #pragma unroll
    for (int i = 0; i < NF; ++i) {
        float w = s_w1[(o<<6) | ((i + o) & 63)];
        float4 a = *(const float4*)&s_a[i*4];
        u[0] += w*a.x; u[1] += w*a.y; u[2] += w*a.z; u[3] += w*a.w;
    }
    float m = 0.25f*((v[0]+0.1f*u[0]) + (v[1]+0.1f*u[1]) + (v[2]+0.1f*u[2]) + (v[3]+0.1f*u[3]));
    g_hvec[b*NF+o] = m;
}

// ---------------- latent head: lin_res x2 + final linear -> d_out[0..4095] ----------
__global__ void __launch_bounds__(512) k_head(
    const float* __restrict__ l1_sw, const float* __restrict__ l1_sb,
    const float* __restrict__ l1_w1, const float* __restrict__ l1_b1,
    const float* __restrict__ l1_w2, const float* __restrict__ l1_b2,
    const float* __restrict__ l2_w1, const float* __restrict__ l2_b1,
    const float* __restrict__ l2_w2, const float* __restrict__ l2_b2,
    const float* __restrict__ lo_w,  const float* __restrict__ lo_b,
    float* __restrict__ lat)
{
    __shared__ float s_h[NF], s_ha[NF];
    __shared__ float s_t[2*LATD];
    __shared__ float s_u[LATD];
    __shared__ float s_hh[LATD];
    const int j = threadIdx.x, b = blockIdx.x;
    if (j < NF) { float h = g_hvec[b*NF+j]; s_h[j] = h; s_ha[j] = lrelu(h); }
    __syncthreads();
    // layer 1 (with skip weights)
    float xs = l1_sb[j];
    for (int i = 0; i < NF; ++i) xs += s_h[i]*l1_sw[i*LATD + j];
    float t0 = l1_b1[j], t1 = l1_b1[j+LATD];
    for (int i = 0; i < NF; ++i) {
        float a = s_ha[i];
        t0 += a*l1_w1[i*2*LATD + j];
        t1 += a*l1_w1[i*2*LATD + j + LATD];
    }
    s_t[j] = lrelu(t0); s_t[j+LATD] = lrelu(t1);
    __syncthreads();
    float v = l1_b2[j];
    for (int i = 0; i < 2*LATD; ++i) v += s_t[i]*l1_w2[(size_t)i*LATD + j];
    float hh = xs + 0.1f*v;
    s_hh[j] = hh; s_u[j] = lrelu(hh);
    __syncthreads();
    // layer 2 (identity skip)
    float t2 = l2_b1[j];
    for (int i = 0; i < LATD; ++i) t2 += s_u[i]*l2_w1[(size_t)i*LATD + j];
    __syncthreads();
    s_u[j] = lrelu(t2);
    __syncthreads();
    float v2 = l2_b2[j];
    for (int i = 0; i < LATD; ++i) v2 += s_u[i]*l2_w2[(size_t)i*LATD + j];
    float g = s_hh[j] + 0.1f*v2;
    s_t[j] = g;
    __syncthreads();
    // final linear
    float outv = lo_b[j];
    for (int i = 0; i < LATD; ++i) outv += s_t[i]*lo_w[(size_t)i*LATD + j];
    lat[b*LATD + j] = outv;
}

// ---------------- host launcher ----------------
extern "C" void kernel_launch(void* const* d_in, const int* in_sizes, int n_in,
                              void* d_out, int out_size)
{
    const float* x        = (const float*)d_in[0];
    const float* inj      = (const float*)d_in[1];
    const float* leak     = (const float*)d_in[2];
    const float* in_w     = (const float*)d_in[3];
    const float* in_b     = (const float*)d_in[4];
    const float* inrb_w0  = (const float*)d_in[5];
    const float* inrb_b0  = (const float*)d_in[6];
    const float* inrb_w1  = (const float*)d_in[7];
    const float* inrb_b1  = (const float*)d_in[8];
    const float* hyp_w    = (const float*)d_in[9];
    const float* hyp_b    = (const float*)d_in[10];
    const float* outrb_w0 = (const float*)d_in[11];
    const float* outrb_b0 = (const float*)d_in[12];
    const float* outrb_w1 = (const float*)d_in[13];
    const float* outrb_b1 = (const float*)d_in[14];
    const float* l1_sw    = (const float*)d_in[15];
    const float* l1_sb    = (const float*)d_in[16];
    const float* l1_w1    = (const float*)d_in[17];
    const float* l1_b1    = (const float*)d_in[18];
    const float* l1_w2    = (const float*)d_in[19];
    const float* l1_b2    = (const float*)d_in[20];
    const float* l2_w1    = (const float*)d_in[21];
    const float* l2_b1    = (const float*)d_in[22];
    const float* l2_w2    = (const float*)d_in[23];
    const float* l2_b2    = (const float*)d_in[24];
    const float* lo_w     = (const float*)d_in[25];
    const float* lo_b     = (const float*)d_in[26];
    float* out = (float*)d_out;

    float *p_perc, *p_h1, *p_h2, *p_full, *p_out, *p_wAT, *p_wMT, *p_wCDT, *p_bA, *p_bM, *p_bCD;
    cudaGetSymbolAddress((void**)&p_perc, g_perc);
    cudaGetSymbolAddress((void**)&p_h1,   g_h1);
    cudaGetSymbolAddress((void**)&p_h2,   g_h2);
    cudaGetSymbolAddress((void**)&p_full, g_full);
    cudaGetSymbolAddress((void**)&p_out,  g_out);
    cudaGetSymbolAddress((void**)&p_wAT,  g_wAT);
    cudaGetSymbolAddress((void**)&p_wMT,  g_wMT);
    cudaGetSymbolAddress((void**)&p_wCDT, g_wCDT);
    cudaGetSymbolAddress((void**)&p_bA,   g_bA);
    cudaGetSymbolAddress((void**)&p_bM,   g_bM);
    cudaGetSymbolAddress((void**)&p_bCD,  g_bCD);

    size_t off = (size_t)BB*LATD;  // lat occupies [0, 4096)
    k_input<<<dim3(P0/64, BB), 64>>>(x, in_w, in_b, inrb_w0, inrb_b0, inrb_w1, inrb_b1, out + off);
    k_hyper<<<(PT + 127)/128, 128>>>(inj, hyp_w, hyp_b);
    k_tr<<<dim3((61760 + 255)/256, BB), 256>>>();
    off += (size_t)BB*NF*P0;

    int H = 128;
    for (int it = 0; it < 6; ++it) {
        int P = H*H;
        k_sobel<<<(BB*NF*P + 255)/256, 256>>>(H);
        int tilesM = (P + 127)/128;
        k_gemm<0><<<dim3(tilesM*2, BB), 256>>>(p_perc, FIN, (long long)FIN*P,
                                               nullptr, 0, 0,
                                               p_wAT, FH, (long long)FIN*FH,
                                               p_bA, FH,
                                               p_h1, (long long)FH*P,
                                               nullptr, nullptr, P, tilesM);
        k_gemm<0><<<dim3(tilesM*2, BB), 256>>>(p_h1, FH, (long long)FH*P,
                                               nullptr, 0, 0,
                                               p_wMT, FH, (long long)FH*FH,
                                               p_bM, FH,
                                               p_h2, (long long)FH*P,
                                               nullptr, nullptr, P, tilesM);
        k_gemm<1><<<dim3(tilesM, BB), 256>>>(p_h2, FH, (long long)FH*P,
                                             p_perc, FIN, (long long)FIN*P,
                                             p_wCDT, NF, (long long)320*NF,
                                             p_bCD, NF,
                                             p_full, (long long)NF*P,
                                             p_out, leak, P, tilesM);
        int Hn = H/2, Pn = Hn*Hn;
        k_down<<<(BB*NF*Pn + 255)/256, 256>>>(H, out + off);
        off += (size_t)BB*NF*Pn;
        H = Hn;
    }
    k_tail<<<BB, 64>>>(outrb_w0, outrb_b0, outrb_w1, outrb_b1);
    k_head<<<BB, 512>>>(l1_sw, l1_sb, l1_w1, l1_b1, l1_w2, l1_b2,
                        l2_w1, l2_b1, l2_w2, l2_b2, lo_w, lo_b, out);
}

// round 2
// speedup vs baseline: 1.0617x; 1.0617x over previous
#include <cuda_runtime.h>
#include <cstddef>

#define BB   8
#define NF   64
#define FIN  192
#define FH   128
#define LATD 512
#define PT   61824
#define P0   16384   // 128*128

// ---------------- scratch (device globals; no allocation) ----------------
__device__ float g_out [BB*NF *P0];
__device__ float g_perc[BB*FIN*P0];
__device__ float g_h1  [BB*FH *P0];
__device__ float g_h2  [BB*FH *P0];
__device__ float g_full[BB*NF *P0];
__device__ float g_dyn [BB*PT];
__device__ float g_wAT [BB*FIN*FH];   // [192][128] per sample (w_in^T)
__device__ float g_wMT [BB*FH*FH];    // [128][128] per sample (w_mid^T)
__device__ float g_wCDT[BB*320*NF];   // [320][64]: rows 0..127 w_out^T, 128..319 w_sk^T
__device__ float g_bA  [BB*FH];
__device__ float g_bM  [BB*FH];
__device__ float g_bCD [BB*NF];
__device__ float g_hvec[BB*NF];

__device__ __forceinline__ float lrelu(float x){ return x > 0.0f ? x : 0.2f*x; }

__device__ __forceinline__ void fma2(unsigned long long &d, unsigned long long a, unsigned long long b) {
    asm("fma.rn.f32x2 %0, %1, %2, %0;" : "+l"(d) : "l"(a), "l"(b));
}
__device__ __forceinline__ float2 unpack2(unsigned long long v) {
    float2 r; asm("mov.b64 {%0,%1}, %2;" : "=f"(r.x), "=f"(r.y) : "l"(v)); return r;
}

// ---------------- input conv1x1 + res_block, writes emb0 ----------------
__global__ void k_input(const float* __restrict__ x, const float* __restrict__ in_w,
                        const float* __restrict__ in_b,
                        const float* __restrict__ w0, const float* __restrict__ b0,
                        const float* __restrict__ w1, const float* __restrict__ b1,
                        float* __restrict__ emb0)
{
    __shared__ float s_w0[NF*NF];   // swizzled: [o][ (i+o)&63 ]
    __shared__ float s_w1[NF*NF];
    __shared__ float s_a [NF*4];    // [i][py]
    const int o = threadIdx.x;
    const int b = blockIdx.y;
    const int pbase = blockIdx.x * 64;
    for (int e = o; e < NF*NF; e += 64) {
        int r = e >> 6, i = e & 63;
        s_w0[(r<<6) | ((i + r) & 63)] = w0[e];
        s_w1[(r<<6) | ((i + r) & 63)] = w1[e];
    }
    const float iw0 = in_w[o*3+0], iw1 = in_w[o*3+1], iw2 = in_w[o*3+2];
    const float bin = in_b[o], bb0 = b0[o], bb1 = b1[o];
    __syncthreads();
    for (int it = 0; it < 16; ++it) {
        const int p4 = pbase + it*4;
        float v[4];
        #pragma unroll
        for (int py = 0; py < 4; ++py) {
            int p = p4 + py;
            v[py] = bin + iw0*x[(b*3+0)*P0+p] + iw1*x[(b*3+1)*P0+p] + iw2*x[(b*3+2)*P0+p];
        }
        __syncthreads();
        *(float4*)&s_a[o*4] = make_float4(lrelu(v[0]),lrelu(v[1]),lrelu(v[2]),lrelu(v[3]));
        __syncthreads();
        float t[4] = {bb0,bb0,bb0,bb0};
        #pragma unroll
        for (int i = 0; i < NF; ++i) {
            float w = s_w0[(o<<6) | ((i + o) & 63)];
            float4 a = *(const float4*)&s_a[i*4];
            t[0] += w*a.x; t[1] += w*a.y; t[2] += w*a.z; t[3] += w*a.w;
        }
        __syncthreads();
        *(float4*)&s_a[o*4] = make_float4(lrelu(t[0]),lrelu(t[1]),lrelu(t[2]),lrelu(t[3]));
        __syncthreads();
        float u[4] = {bb1,bb1,bb1,bb1};
        #pragma unroll
        for (int i = 0; i < NF; ++i) {
            float w = s_w1[(o<<6) | ((i + o) & 63)];
            float4 a = *(const float4*)&s_a[i*4];
            u[0] += w*a.x; u[1] += w*a.y; u[2] += w*a.z; u[3] += w*a.w;
        }
        #pragma unroll
        for (int py = 0; py < 4; ++py) {
            float r = v[py] + 0.1f*u[py];
            size_t idx = (size_t)(b*NF+o)*P0 + p4 + py;
            g_out[idx] = r;
            emb0[idx]  = r;
        }
    }
}

// ---------------- hypernet: dyn = inj_lat @ hyp_w + hyp_b ----------------
__global__ void k_hyper(const float* __restrict__ inj, const float* __restrict__ hw,
                        const float* __restrict__ hb)
{
    __shared__ float s_inj[BB*LATD];
    const int tid = threadIdx.x;  // 128
    for (int e = tid; e < BB*LATD; e += 128) s_inj[e] = inj[e];
    __syncthreads();
    const int j = blockIdx.x*128 + tid;
    if (j >= PT) return;
    float acc[BB];
    #pragma unroll
    for (int b = 0; b < BB; ++b) acc[b] = 0.f;
    for (int k = 0; k < LATD; ++k) {
        float w = hw[(size_t)k*PT + j];
        #pragma unroll
        for (int b = 0; b < BB; ++b) acc[b] += s_inj[b*LATD+k]*w;
    }
    const float bb = hb[j];
    #pragma unroll
    for (int b = 0; b < BB; ++b) g_dyn[(size_t)b*PT + j] = acc[b] + bb;
}

// ---------------- transpose dyn params into GEMM-friendly layout ----------------
__global__ void k_tr()
{
    const int b = blockIdx.y;
    int i = blockIdx.x*256 + threadIdx.x;
    const float* d = g_dyn + (size_t)b*PT;
    if (i < FIN*FH) { int k = i/FH, o = i%FH; g_wAT[(size_t)b*FIN*FH + i] = d[o*FIN + k]; return; }
    i -= FIN*FH;
    if (i < FH*FH)  { int k = i/FH, o = i%FH; g_wMT[(size_t)b*FH*FH + i] = d[24704 + o*FH + k]; return; }
    i -= FH*FH;
    if (i < 320*NF) { int k = i/NF, o = i%NF;
        g_wCDT[(size_t)b*320*NF + i] = (k < FH) ? d[41216 + o*FH + k]
                                                : d[49472 + o*FIN + (k-FH)];
        return; }
    i -= 320*NF;
    if (i < FH) { g_bA[b*FH+i] = d[24576+i]; return; }
    i -= FH;
    if (i < FH) { g_bM[b*FH+i] = d[41088+i]; return; }
    i -= FH;
    if (i < NF) { g_bCD[b*NF+i] = d[49408+i] + d[61760+i]; return; }
}

// ---------------- sin_sobel: g_out -> g_perc (id | dx | dy), zero pad ----------------
__global__ void k_sobel(int H, int lgH)
{
    const int P = H*H;
    const int idx = blockIdx.x*256 + threadIdx.x;
    if (idx >= BB*NF*P) return;
    const int p = idx & (P-1);
    const int c = (idx >> (2*lgH)) & (NF-1);
    const int b = idx >> (2*lgH + 6);
    const int y = p >> lgH, xx = p & (H-1);
    const float* src = g_out + (size_t)(b*NF + c)*P;
    float c00 = src[p];
    float m00 = (y>0   && xx>0  ) ? src[((y-1)<<lgH)+xx-1] : 0.f;
    float m01 = (y>0            ) ? src[((y-1)<<lgH)+xx  ] : 0.f;
    float m02 = (y>0   && xx<H-1) ? src[((y-1)<<lgH)+xx+1] : 0.f;
    float m10 = (         xx>0  ) ? src[( y   <<lgH)+xx-1] : 0.f;
    float m12 = (         xx<H-1) ? src[( y   <<lgH)+xx+1] : 0.f;
    float m20 = (y<H-1 && xx>0  ) ? src[((y+1)<<lgH)+xx-1] : 0.f;
    float m21 = (y<H-1          ) ? src[((y+1)<<lgH)+xx  ] : 0.f;
    float m22 = (y<H-1 && xx<H-1) ? src[((y+1)<<lgH)+xx+1] : 0.f;
    float sx = (m00 - m02 + 2.f*(m10 - m12) + m20 - m22) * 0.125f;
    float sy = (m00 + 2.f*m01 + m02 - m20 - 2.f*m21 - m22) * 0.125f;
    float* dst = g_perc + (size_t)b*FIN*P;
    dst[(size_t) c      *P + p] = c00;
    dst[(size_t)(NF+c)  *P + p] = sx;
    dst[(size_t)(2*NF+c)*P + p] = sy;
}

// ---------------- per-sample SGEMM via packed fma.rn.f32x2 ----------------
// C[n][p] = sum_k A[k][p] * Wt[k][n] (+epilogue)
// EPI 0: C = lrelu(v + bias)          EPI 1: C = O + leak * (v + bias)
template<int EPI>
__global__ void __launch_bounds__(256) k_gemm(
    const float* __restrict__ A1, int K1, long long sA1,
    const float* __restrict__ A2, int K2, long long sA2,
    const float* __restrict__ Wt, int ldw, long long sW,
    const float* __restrict__ bias, int sBias,
    float* __restrict__ C, long long sC,
    const float* __restrict__ O, const float* __restrict__ leak_ptr,
    int P, int tilesM)
{
    const int BM = 128, BN = 64, BK = 16;
    const int b = blockIdx.y;
    const int tileM = blockIdx.x % tilesM;
    const int n0 = (blockIdx.x / tilesM) * BN;
    const int m0 = tileM * BM;
    A1 += (size_t)b * sA1;
    if (A2) A2 += (size_t)b * sA2;
    Wt   += (size_t)b * sW;
    bias += (size_t)b * sBias;
    C    += (size_t)b * sC;

    __shared__ float As[2][BK][BM];
    __shared__ float Wd[2][BK][2*BN];   // duplicated pairs (w,w)

    const int tid = threadIdx.x;
    const int tm = tid & 15, tn = tid >> 4;
    // loader indices
    const int la_k = tid >> 5;            // 0..7 (second half at +8)
    const int la_m = (tid & 31) << 2;
    const int lw_k = tid >> 4;            // 0..15
    const int lw_n = (tid & 15) << 2;

    unsigned long long acc[4][4];
    #pragma unroll
    for (int j = 0; j < 4; ++j)
        #pragma unroll
        for (int i = 0; i < 4; ++i) acc[j][i] = 0ULL;

    const int K = K1 + K2;
    const int T = K / BK;

    float4 pa0, pa1, pw;
    auto ldA = [&](int kk, int m) -> float4 {
        const float* src = (kk < K1) ? (A1 + (size_t)kk*P) : (A2 + (size_t)(kk-K1)*P);
        if (m + 4 <= P) return *(const float4*)(src + m);
        float4 v;
        v.x = (m   < P) ? src[m  ] : 0.f;
        v.y = (m+1 < P) ? src[m+1] : 0.f;
        v.z = (m+2 < P) ? src[m+2] : 0.f;
        v.w = 0.f;
        return v;
    };
    auto prefetch = [&](int k0) {
        pa0 = ldA(k0 + la_k,     m0 + la_m);
        pa1 = ldA(k0 + la_k + 8, m0 + la_m);
        pw  = *(const float4*)(Wt + (size_t)(k0 + lw_k)*ldw + n0 + lw_n);
    };
    auto store_tile = [&](int nb) {
        *(float4*)&As[nb][la_k  ][la_m] = pa0;
        *(float4*)&As[nb][la_k+8][la_m] = pa1;
        float* wd = &Wd[nb][lw_k][lw_n*2];
        *(float4*)(wd  ) = make_float4(pw.x, pw.x, pw.y, pw.y);
        *(float4*)(wd+4) = make_float4(pw.z, pw.z, pw.w, pw.w);
    };

    prefetch(0);
    store_tile(0);
    __syncthreads();

    for (int t = 0; t < T; ++t) {
        const int buf = t & 1;
        if (t + 1 < T) prefetch((t + 1) * BK);
        const float* asb = &As[buf][0][tm*8];
        const float* wsb = &Wd[buf][0][tn*8];
        #pragma unroll
        for (int kc = 0; kc < BK; ++kc) {
            ulonglong2 aA = *(const ulonglong2*)(asb + kc*BM);
            ulonglong2 aB = *(const ulonglong2*)(asb + kc*BM + 4);
            ulonglong2 wA = *(const ulonglong2*)(wsb + kc*2*BN);
            ulonglong2 wB = *(const ulonglong2*)(wsb + kc*2*BN + 4);
            fma2(acc[0][0], wA.x, aA.x); fma2(acc[0][1], wA.x, aA.y);
            fma2(acc[0][2], wA.x, aB.x); fma2(acc[0][3], wA.x, aB.y);
            fma2(acc[1][0], wA.y, aA.x); fma2(acc[1][1], wA.y, aA.y);
            fma2(acc[1][2], wA.y, aB.x); fma2(acc[1][3], wA.y, aB.y);
            fma2(acc[2][0], wB.x, aA.x); fma2(acc[2][1], wB.x, aA.y);
            fma2(acc[2][2], wB.x, aB.x); fma2(acc[2][3], wB.x, aB.y);
            fma2(acc[3][0], wB.y, aA.x); fma2(acc[3][1], wB.y, aA.y);
            fma2(acc[3][2], wB.y, aB.x); fma2(acc[3][3], wB.y, aB.y);
        }
        if (t + 1 < T) store_tile(buf ^ 1);
        __syncthreads();
    }

    float lk = 0.f;
    if (EPI == 1) { lk = *leak_ptr; lk = fminf(fmaxf(lk, 0.001f), 1000.f); }
    #pragma unroll
    for (int j = 0; j < 4; ++j) {
        const int n = n0 + tn*4 + j;
        const float bv = bias[n];
        #pragma unroll
        for (int i = 0; i < 4; ++i) {
            float2 f = unpack2(acc[j][i]);
            const int m = m0 + tm*8 + i*2;
            float vv[2] = {f.x + bv, f.y + bv};
            #pragma unroll
            for (int q = 0; q < 2; ++q) {
                if (m + q < P) {
                    size_t off = (size_t)n*P + m + q;
                    if (EPI == 0) C[off] = lrelu(vv[q]);
                    else          C[off] = O[(size_t)b*sC + off] + lk*vv[q];
                }
            }
        }
    }
}

// ---------------- gauss 3x3 (zero pad) + 2x2 mean, writes g_out + emb ----------------
__global__ void k_down(int H, int lgH, float* __restrict__ emb)
{
    const int Hn = H >> 1, Pn = Hn*Hn;
    const int lgHn = lgH - 1;
    const int idx = blockIdx.x*256 + threadIdx.x;
    if (idx >= BB*NF*Pn) return;
    const int p = idx & (Pn-1);
    const int c = (idx >> (2*lgHn)) & (NF-1);
    const int b = idx >> (2*lgHn + 6);
    const int oy = p >> lgHn, ox = p & (Hn-1);
    const float* src = g_full + (size_t)(b*NF+c)*H*H;
    const float G0 = 0.27406861906119695f;
    const float G1 = 0.72593138093880305f;
    const float u4[4] = {G0, G1, G1, G0};
    float acc = 0.f;
    #pragma unroll
    for (int r = 0; r < 4; ++r) {
        int yy = 2*oy + r - 1;
        if (yy < 0 || yy >= H) continue;
        float rowacc = 0.f;
        #pragma unroll
        for (int cc = 0; cc < 4; ++cc) {
            int xx = 2*ox + cc - 1;
            if (xx < 0 || xx >= H) continue;
            rowacc += u4[cc]*src[(yy<<lgH)+xx];
        }
        acc += u4[r]*rowacc;
    }
    acc *= 0.25f;
    const size_t o = (size_t)(b*NF+c)*Pn + p;
    g_out[o] = acc;
    emb[o]   = acc;
}

// ---------------- tail res_block at 2x2 + spatial mean -> g_hvec ----------------
__global__ void k_tail(const float* __restrict__ w0, const float* __restrict__ b0,
                       const float* __restrict__ w1, const float* __restrict__ b1)
{
    __shared__ float s_w0[NF*NF], s_w1[NF*NF], s_a[NF*4];
    const int o = threadIdx.x, b = blockIdx.x;
    for (int e = o; e < NF*NF; e += 64) {
        int r = e >> 6, i = e & 63;
        s_w0[(r<<6) | ((i + r) & 63)] = w0[e];
        s_w1[(r<<6) | ((i + r) & 63)] = w1[e];
    }
    const float bb0 = b0[o], bb1 = b1[o];
    __syncthreads();
    float v[4];
    #pragma unroll
    for (int py = 0; py < 4; ++py) v[py] = g_out[(size_t)(b*NF+o)*4 + py];
    *(float4*)&s_a[o*4] = make_float4(lrelu(v[0]),lrelu(v[1]),lrelu(v[2]),lrelu(v[3]));
    __syncthreads();
    float t[4] = {bb0,bb0,bb0,bb0};
    #pragma unroll
    for (int i = 0; i < NF; ++i) {
        float w = s_w0[(o<<6) | ((i + o) & 63)];
        float4 a = *(const float4*)&s_a[i*4];
        t[0] += w*a.x; t[1] += w*a.y; t[2] += w*a.z; t[3] += w*a.w;
    }
    __syncthreads();
    *(float4*)&s_a[o*4] = make_float4(lrelu(t[0]),lrelu(t[1]),lrelu(t[2]),lrelu(t[3]));
    __syncthreads();
    float u[4] = {bb1,bb1,bb1,bb1};
    #pragma unroll
    for (int i = 0; i < NF; ++i) {
        float w = s_w1[(o<<6) | ((i + o) & 63)];
        float4 a = *(const float4*)&s_a[i*4];
        u[0] += w*a.x; u[1] += w*a.y; u[2] += w*a.z; u[3] += w*a.w;
    }
    float m = 0.25f*((v[0]+0.1f*u[0]) + (v[1]+0.1f*u[1]) + (v[2]+0.1f*u[2]) + (v[3]+0.1f*u[3]));
    g_hvec[b*NF+o] = m;
}

// ---------------- latent head ----------------
__global__ void __launch_bounds__(512) k_head(
    const float* __restrict__ l1_sw, const float* __restrict__ l1_sb,
    const float* __restrict__ l1_w1, const float* __restrict__ l1_b1,
    const float* __restrict__ l1_w2, const float* __restrict__ l1_b2,
    const float* __restrict__ l2_w1, const float* __restrict__ l2_b1,
    const float* __restrict__ l2_w2, const float* __restrict__ l2_b2,
    const float* __restrict__ lo_w,  const float* __restrict__ lo_b,
    float* __restrict__ lat)
{
    __shared__ float s_h[NF], s_ha[NF];
    __shared__ float s_t[2*LATD];
    __shared__ float s_u[LATD];
    __shared__ float s_hh[LATD];
    const int j = threadIdx.x, b = blockIdx.x;
    if (j < NF) { float h = g_hvec[b*NF+j]; s_h[j] = h; s_ha[j] = lrelu(h); }
    __syncthreads();
    float xs = l1_sb[j];
    for (int i = 0; i < NF; ++i) xs += s_h[i]*l1_sw[i*LATD + j];
    float t0 = l1_b1[j], t1 = l1_b1[j+LATD];
    for (int i = 0; i < NF; ++i) {
        float a = s_ha[i];
        t0 += a*l1_w1[i*2*LATD + j];
        t1 += a*l1_w1[i*2*LATD + j + LATD];
    }
    s_t[j] = lrelu(t0); s_t[j+LATD] = lrelu(t1);
    __syncthreads();
    float v = l1_b2[j];
    for (int i = 0; i < 2*LATD; ++i) v += s_t[i]*l1_w2[(size_t)i*LATD + j];
    float hh = xs + 0.1f*v;
    s_hh[j] = hh; s_u[j] = lrelu(hh);
    __syncthreads();
    float t2 = l2_b1[j];
    for (int i = 0; i < LATD; ++i) t2 += s_u[i]*l2_w1[(size_t)i*LATD + j];
    __syncthreads();
    s_u[j] = lrelu(t2);
    __syncthreads();
    float v2 = l2_b2[j];
    for (int i = 0; i < LATD; ++i) v2 += s_u[i]*l2_w2[(size_t)i*LATD + j];
    float g = s_hh[j] + 0.1f*v2;
    s_t[j] = g;
    __syncthreads();
    float outv = lo_b[j];
    for (int i = 0; i < LATD; ++i) outv += s_t[i]*lo_w[(size_t)i*LATD + j];
    lat[b*LATD + j] = outv;
}

// ---------------- host launcher ----------------
extern "C" void kernel_launch(void* const* d_in, const int* in_sizes, int n_in,
                              void* d_out, int out_size)
{
    const float* x        = (const float*)d_in[0];
    const float* inj      = (const float*)d_in[1];
    const float* leak     = (const float*)d_in[2];
    const float* in_w     = (const float*)d_in[3];
    const float* in_b     = (const float*)d_in[4];
    const float* inrb_w0  = (const float*)d_in[5];
    const float* inrb_b0  = (const float*)d_in[6];
    const float* inrb_w1  = (const float*)d_in[7];
    const float* inrb_b1  = (const float*)d_in[8];
    const float* hyp_w    = (const float*)d_in[9];
    const float* hyp_b    = (const float*)d_in[10];
    const float* outrb_w0 = (const float*)d_in[11];
    const float* outrb_b0 = (const float*)d_in[12];
    const float* outrb_w1 = (const float*)d_in[13];
    const float* outrb_b1 = (const float*)d_in[14];
    const float* l1_sw    = (const float*)d_in[15];
    const float* l1_sb    = (const float*)d_in[16];
    const float* l1_w1    = (const float*)d_in[17];
    const float* l1_b1    = (const float*)d_in[18];
    const float* l1_w2    = (const float*)d_in[19];
    const float* l1_b2    = (const float*)d_in[20];
    const float* l2_w1    = (const float*)d_in[21];
    const float* l2_b1    = (const float*)d_in[22];
    const float* l2_w2    = (const float*)d_in[23];
    const float* l2_b2    = (const float*)d_in[24];
    const float* lo_w     = (const float*)d_in[25];
    const float* lo_b     = (const float*)d_in[26];
    float* out = (float*)d_out;

    float *p_perc, *p_h1, *p_h2, *p_full, *p_out, *p_wAT, *p_wMT, *p_wCDT, *p_bA, *p_bM, *p_bCD;
    cudaGetSymbolAddress((void**)&p_perc, g_perc);
    cudaGetSymbolAddress((void**)&p_h1,   g_h1);
    cudaGetSymbolAddress((void**)&p_h2,   g_h2);
    cudaGetSymbolAddress((void**)&p_full, g_full);
    cudaGetSymbolAddress((void**)&p_out,  g_out);
    cudaGetSymbolAddress((void**)&p_wAT,  g_wAT);
    cudaGetSymbolAddress((void**)&p_wMT,  g_wMT);
    cudaGetSymbolAddress((void**)&p_wCDT, g_wCDT);
    cudaGetSymbolAddress((void**)&p_bA,   g_bA);
    cudaGetSymbolAddress((void**)&p_bM,   g_bM);
    cudaGetSymbolAddress((void**)&p_bCD,  g_bCD);

    size_t off = (size_t)BB*LATD;  // lat occupies [0, 4096)
    k_input<<<dim3(P0/64, BB), 64>>>(x, in_w, in_b, inrb_w0, inrb_b0, inrb_w1, inrb_b1, out + off);
    k_hyper<<<(PT + 127)/128, 128>>>(inj, hyp_w, hyp_b);
    k_tr<<<dim3((61760 + 255)/256, BB), 256>>>();
    off += (size_t)BB*NF*P0;

    int H = 128, lgH = 7;
    for (int it = 0; it < 6; ++it) {
        int P = H*H;
        k_sobel<<<(BB*NF*P + 255)/256, 256>>>(H, lgH);
        int tilesM = (P + 127)/128;
        k_gemm<0><<<dim3(tilesM*2, BB), 256>>>(p_perc, FIN, (long long)FIN*P,
                                               nullptr, 0, 0,
                                               p_wAT, FH, (long long)FIN*FH,
                                               p_bA, FH,
                                               p_h1, (long long)FH*P,
                                               nullptr, nullptr, P, tilesM);
        k_gemm<0><<<dim3(tilesM*2, BB), 256>>>(p_h1, FH, (long long)FH*P,
                                               nullptr, 0, 0,
                                               p_wMT, FH, (long long)FH*FH,
                                               p_bM, FH,
                                               p_h2, (long long)FH*P,
                                               nullptr, nullptr, P, tilesM);
        k_gemm<1><<<dim3(tilesM, BB), 256>>>(p_h2, FH, (long long)FH*P,
                                             p_perc, FIN, (long long)FIN*P,
                                             p_wCDT, NF, (long long)320*NF,
                                             p_bCD, NF,
                                             p_full, (long long)NF*P,
                                             p_out, leak, P, tilesM);
        int Hn = H/2, Pn = Hn*Hn;
        k_down<<<(BB*NF*Pn + 255)/256, 256>>>(H, lgH, out + off);
        off += (size_t)BB*NF*Pn;
        H = Hn; lgH -= 1;
    }
    k_tail<<<BB, 64>>>(outrb_w0, outrb_b0, outrb_w1, outrb_b1);
    k_head<<<BB, 512>>>(l1_sw, l1_sb, l1_w1, l1_b1, l1_w2, l1_b2,
                        l2_w1, l2_b1, l2_w2, l2_b2, lo_w, lo_b, out);
}

// round 3
// speedup vs baseline: 1.6212x; 1.5270x over previous
#include <cuda_runtime.h>
#include <cstddef>

#define BB   8
#define NF   64
#define FIN  192
#define FH   128
#define LATD 512
#define PT   61824
#define P0   16384   // 128*128

// ---------------- scratch (device globals; no allocation) ----------------
__device__ float g_out [BB*NF *P0];
__device__ float g_perc[BB*FIN*P0];
__device__ float g_h1  [BB*FH *P0];
__device__ float g_h2  [BB*FH *P0];
__device__ float g_full[BB*NF *P0];
__device__ float g_dyn [BB*PT];
__device__ float g_wAT [BB*FIN*FH];   // [192][128] per sample (w_in^T)
__device__ float g_wMT [BB*FH*FH];    // [128][128] per sample (w_mid^T)
__device__ float g_wCDT[BB*320*NF];   // [320][64]: rows 0..127 w_out^T, 128..319 w_sk^T
__device__ float g_bA  [BB*FH];
__device__ float g_bM  [BB*FH];
__device__ float g_bCD [BB*NF];
__device__ float g_hvec[BB*NF];
__device__ float g_wRB [2*NF*NF];     // transposed inrb_w0, inrb_w1 (shared across batch)

__device__ __forceinline__ float lrelu(float x){ return x > 0.0f ? x : 0.2f*x; }
__device__ __forceinline__ float4 lrelu4(float4 v){
    return make_float4(lrelu(v.x), lrelu(v.y), lrelu(v.z), lrelu(v.w));
}
__device__ __forceinline__ void fma2(unsigned long long &d, unsigned long long a, unsigned long long b) {
    asm("fma.rn.f32x2 %0, %1, %2, %0;" : "+l"(d) : "l"(a), "l"(b));
}
__device__ __forceinline__ float2 unpack2(unsigned long long v) {
    float2 r; asm("mov.b64 {%0,%1}, %2;" : "=f"(r.x), "=f"(r.y) : "l"(v)); return r;
}
__device__ __forceinline__ unsigned long long pack2(float lo, float hi) {
    unsigned long long r; asm("mov.b64 %0, {%1,%2};" : "=l"(r) : "f"(lo), "f"(hi)); return r;
}

// ---------------- input 1x1 conv (3 -> 64): y -> g_full ----------------
__global__ void k_inconv(const float* __restrict__ x, const float* __restrict__ in_w,
                         const float* __restrict__ in_b)
{
    const int idx = blockIdx.x*256 + threadIdx.x;   // BB*NF*P0/4 = 2^21
    const int p4 = (idx & 4095) << 2;
    const int o  = (idx >> 12) & 63;
    const int b  = idx >> 18;
    const float w0 = in_w[o*3+0], w1 = in_w[o*3+1], w2 = in_w[o*3+2], bv = in_b[o];
    const float* xp = x + (size_t)(b*3)*P0 + p4;
    float4 a = *(const float4*)xp;
    float4 c = *(const float4*)(xp + P0);
    float4 d = *(const float4*)(xp + 2*P0);
    float4 r;
    r.x = bv + w0*a.x + w1*c.x + w2*d.x;
    r.y = bv + w0*a.y + w1*c.y + w2*d.y;
    r.z = bv + w0*a.z + w1*c.z + w2*d.z;
    r.w = bv + w0*a.w + w1*c.w + w2*d.w;
    *(float4*)&g_full[(size_t)(b*NF+o)*P0 + p4] = r;
}

// ---------------- transpose static resblock weights ----------------
__global__ void k_trw(const float* __restrict__ w0, const float* __restrict__ w1)
{
    const int i = blockIdx.x*256 + threadIdx.x;   // 8192
    if (i < 4096) { int k = i >> 6, o = i & 63; g_wRB[i] = w0[o*64 + k]; }
    else { int j = i - 4096; int k = j >> 6, o = j & 63; g_wRB[i] = w1[o*64 + k]; }
}

// ---------------- hypernet: dyn = inj_lat @ hyp_w + hyp_b ----------------
__global__ void k_hyper(const float* __restrict__ inj, const float* __restrict__ hw,
                        const float* __restrict__ hb)
{
    __shared__ float s_inj[BB*LATD];
    const int tid = threadIdx.x;  // 128
    for (int e = tid; e < BB*LATD; e += 128) s_inj[e] = inj[e];
    __syncthreads();
    const int j = blockIdx.x*128 + tid;
    if (j >= PT) return;
    float acc[BB];
    #pragma unroll
    for (int b = 0; b < BB; ++b) acc[b] = 0.f;
    for (int k = 0; k < LATD; ++k) {
        float w = hw[(size_t)k*PT + j];
        #pragma unroll
        for (int b = 0; b < BB; ++b) acc[b] += s_inj[b*LATD+k]*w;
    }
    const float bb = hb[j];
    #pragma unroll
    for (int b = 0; b < BB; ++b) g_dyn[(size_t)b*PT + j] = acc[b] + bb;
}

// ---------------- transpose dyn params into GEMM-friendly layout ----------------
__global__ void k_tr()
{
    const int b = blockIdx.y;
    int i = blockIdx.x*256 + threadIdx.x;
    const float* d = g_dyn + (size_t)b*PT;
    if (i < FIN*FH) { int k = i/FH, o = i%FH; g_wAT[(size_t)b*FIN*FH + i] = d[o*FIN + k]; return; }
    i -= FIN*FH;
    if (i < FH*FH)  { int k = i/FH, o = i%FH; g_wMT[(size_t)b*FH*FH + i] = d[24704 + o*FH + k]; return; }
    i -= FH*FH;
    if (i < 320*NF) { int k = i/NF, o = i%NF;
        g_wCDT[(size_t)b*320*NF + i] = (k < FH) ? d[41216 + o*FH + k]
                                                : d[49472 + o*FIN + (k-FH)];
        return; }
    i -= 320*NF;
    if (i < FH) { g_bA[b*FH+i] = d[24576+i]; return; }
    i -= FH;
    if (i < FH) { g_bM[b*FH+i] = d[41088+i]; return; }
    i -= FH;
    if (i < NF) { g_bCD[b*NF+i] = d[49408+i] + d[61760+i]; return; }
}

// ---------------- sin_sobel: g_out -> g_perc, 4 px/thread ----------------
__global__ void k_sobel4(int H, int lgH)
{
    const int P = H*H;
    const int idx = blockIdx.x*256 + threadIdx.x;
    if (idx >= BB*NF*(P>>2)) return;
    const int q  = idx & ((P>>2)-1);
    const int c  = (idx >> (2*lgH-2)) & 63;
    const int b  = idx >> (2*lgH+4);
    const int p4 = q << 2;
    const int y  = p4 >> lgH, x0 = p4 & (H-1);
    const float* src = g_out + (size_t)(b*NF+c)*P;

    float am[6], ac[6], ap[6];
    // row y
    {
        float4 v = *(const float4*)&src[p4];
        ac[0] = (x0 > 0)     ? src[p4-1] : 0.f;
        ac[1] = v.x; ac[2] = v.y; ac[3] = v.z; ac[4] = v.w;
        ac[5] = (x0+4 < H)   ? src[p4+4] : 0.f;
    }
    if (y > 0) {
        int base = (y-1) << lgH;
        float4 v = *(const float4*)&src[base + x0];
        am[0] = (x0 > 0)   ? src[base+x0-1] : 0.f;
        am[1] = v.x; am[2] = v.y; am[3] = v.z; am[4] = v.w;
        am[5] = (x0+4 < H) ? src[base+x0+4] : 0.f;
    } else { am[0]=am[1]=am[2]=am[3]=am[4]=am[5]=0.f; }
    if (y < H-1) {
        int base = (y+1) << lgH;
        float4 v = *(const float4*)&src[base + x0];
        ap[0] = (x0 > 0)   ? src[base+x0-1] : 0.f;
        ap[1] = v.x; ap[2] = v.y; ap[3] = v.z; ap[4] = v.w;
        ap[5] = (x0+4 < H) ? src[base+x0+4] : 0.f;
    } else { ap[0]=ap[1]=ap[2]=ap[3]=ap[4]=ap[5]=0.f; }

    float sx[4], sy[4];
    #pragma unroll
    for (int i = 0; i < 4; ++i) {
        float m00 = am[i], m01 = am[i+1], m02 = am[i+2];
        float m10 = ac[i],               m12 = ac[i+2];
        float m20 = ap[i], m21 = ap[i+1], m22 = ap[i+2];
        sx[i] = (m00 - m02 + 2.f*(m10 - m12) + m20 - m22) * 0.125f;
        sy[i] = (m00 + 2.f*m01 + m02 - m20 - 2.f*m21 - m22) * 0.125f;
    }
    float* dst = g_perc + (size_t)b*FIN*P;
    *(float4*)&dst[(size_t) c      *P + p4] = make_float4(ac[1],ac[2],ac[3],ac[4]);
    *(float4*)&dst[(size_t)(NF+c)  *P + p4] = make_float4(sx[0],sx[1],sx[2],sx[3]);
    *(float4*)&dst[(size_t)(2*NF+c)*P + p4] = make_float4(sy[0],sy[1],sy[2],sy[3]);
}

// ---------------- SGEMM: C[n][p] = sum_k A[k][p] * Wt[k][n] (+epilogue) ----------
// 256 threads, per-thread 8M x 8N via fma.rn.f32x2 (M packed in pairs).
// EPI 0: C = lrelu(v+bias)
// EPI 1: C = O + clip(*leak)*(v+bias)
// EPI 2: C = O + 0.1*(v+bias), dual-store to C2
// ACT : apply lrelu to A elements when staging to smem
template<int BM, int BN, int EPI, bool ACT>
__global__ void __launch_bounds__(256, 1) k_gemm(
    const float* __restrict__ A1, int K1, long long sA1,
    const float* __restrict__ A2, int K2, long long sA2,
    const float* __restrict__ Wt, int ldw, long long sW,
    const float* __restrict__ bias, int sBias,
    float* __restrict__ C, long long sC,
    float* __restrict__ C2,
    const float* __restrict__ O, const float* __restrict__ leak_ptr,
    int P)
{
    constexpr int BK  = 16;
    constexpr int TMC = BM/8;              // threads along M
    constexpr int NA  = BK*BM/1024;        // float4 A loads per thread
    constexpr int NW  = (BK*BN >= 1024) ? BK*BN/1024 : 1;  // float4 W loads per thread

    __shared__ float As[2][BK][BM];
    __shared__ float Ws[2][BK][BN];

    const int b  = blockIdx.y;
    const int m0 = blockIdx.x * BM;
    A1 += (size_t)b * sA1;
    if (A2) A2 += (size_t)b * sA2;
    Wt   += (size_t)b * sW;
    bias += (size_t)b * sBias;

    const int tid = threadIdx.x;
    const int tm = tid % TMC;
    const int tn = tid / TMC;

    unsigned long long acc[2][2][4][2];
    #pragma unroll
    for (int af = 0; af < 2; ++af)
        #pragma unroll
        for (int wf = 0; wf < 2; ++wf)
            #pragma unroll
            for (int j = 0; j < 4; ++j) { acc[af][wf][j][0] = 0ULL; acc[af][wf][j][1] = 0ULL; }

    const int K = K1 + K2;
    const int T = K / BK;

    float4 pa[NA], pw[NW];
    auto prefetch = [&](int k0) {
        #pragma unroll
        for (int l = 0; l < NA; ++l) {
            int f  = tid + l*256;
            int kc = f / (BM/4);
            int mv = (f % (BM/4)) * 4;
            int kk = k0 + kc;
            int m  = m0 + mv;
            const float* src = (kk < K1) ? (A1 + (size_t)kk*P) : (A2 + (size_t)(kk-K1)*P);
            pa[l] = (m < P) ? *(const float4*)(src + m) : make_float4(0.f,0.f,0.f,0.f);
        }
        #pragma unroll
        for (int l = 0; l < NW; ++l) {
            int f  = tid + l*256;
            int kc = f / (BN/4);
            int nv = (f % (BN/4)) * 4;
            pw[l] = *(const float4*)(Wt + (size_t)(k0+kc)*ldw + nv);
        }
    };
    auto store_tile = [&](int nb) {
        #pragma unroll
        for (int l = 0; l < NA; ++l) {
            int f  = tid + l*256;
            int kc = f / (BM/4);
            int mv = (f % (BM/4)) * 4;
            *(float4*)&As[nb][kc][mv] = ACT ? lrelu4(pa[l]) : pa[l];
        }
        #pragma unroll
        for (int l = 0; l < NW; ++l) {
            int f  = tid + l*256;
            int kc = f / (BN/4);
            int nv = (f % (BN/4)) * 4;
            *(float4*)&Ws[nb][kc][nv] = pw[l];
        }
    };

    prefetch(0);
    store_tile(0);
    __syncthreads();

    for (int t = 0; t < T; ++t) {
        const int buf = t & 1;
        if (t + 1 < T) prefetch((t + 1) * BK);
        #pragma unroll
        for (int kc = 0; kc < BK; ++kc) {
            ulonglong2 aA = *(const ulonglong2*)&As[buf][kc][tm*4];
            ulonglong2 aB = *(const ulonglong2*)&As[buf][kc][BM/2 + tm*4];
            float4 wa = *(const float4*)&Ws[buf][kc][tn*4];
            float4 wb = *(const float4*)&Ws[buf][kc][BN/2 + tn*4];
            unsigned long long wd[2][4];
            wd[0][0] = pack2(wa.x, wa.x); wd[0][1] = pack2(wa.y, wa.y);
            wd[0][2] = pack2(wa.z, wa.z); wd[0][3] = pack2(wa.w, wa.w);
            wd[1][0] = pack2(wb.x, wb.x); wd[1][1] = pack2(wb.y, wb.y);
            wd[1][2] = pack2(wb.z, wb.z); wd[1][3] = pack2(wb.w, wb.w);
            #pragma unroll
            for (int wf = 0; wf < 2; ++wf)
                #pragma unroll
                for (int j = 0; j < 4; ++j) {
                    fma2(acc[0][wf][j][0], wd[wf][j], aA.x);
                    fma2(acc[0][wf][j][1], wd[wf][j], aA.y);
                    fma2(acc[1][wf][j][0], wd[wf][j], aB.x);
                    fma2(acc[1][wf][j][1], wd[wf][j], aB.y);
                }
        }
        if (t + 1 < T) store_tile(buf ^ 1);
        __syncthreads();
    }

    float lk = 0.1f;
    if (EPI == 1) { lk = *leak_ptr; lk = fminf(fmaxf(lk, 0.001f), 1000.f); }
    #pragma unroll
    for (int af = 0; af < 2; ++af) {
        const int m = m0 + (af ? BM/2 : 0) + tm*4;
        if (m >= P) continue;
        #pragma unroll
        for (int wf = 0; wf < 2; ++wf) {
            #pragma unroll
            for (int j = 0; j < 4; ++j) {
                const int n = (wf ? BN/2 : 0) + tn*4 + j;
                const float bv = bias[n];
                float2 p0 = unpack2(acc[af][wf][j][0]);
                float2 p1 = unpack2(acc[af][wf][j][1]);
                float4 v = make_float4(p0.x+bv, p0.y+bv, p1.x+bv, p1.y+bv);
                const size_t off = (size_t)b*sC + (size_t)n*P + m;
                if (EPI == 0) {
                    *(float4*)&C[off] = lrelu4(v);
                } else {
                    float4 o = *(const float4*)&O[off];
                    v.x = o.x + lk*v.x; v.y = o.y + lk*v.y;
                    v.z = o.z + lk*v.z; v.w = o.w + lk*v.w;
                    *(float4*)&C[off] = v;
                    if (EPI == 2) *(float4*)&C2[off] = v;
                }
            }
        }
    }
}

// ---------------- gauss 3x3 (zero pad) + 2x2 mean, writes g_out + emb ----------------
__global__ void k_down(int H, int lgH, float* __restrict__ emb)
{
    const int Hn = H >> 1, Pn = Hn*Hn;
    const int lgHn = lgH - 1;
    const int idx = blockIdx.x*256 + threadIdx.x;
    if (idx >= BB*NF*Pn) return;
    const int p = idx & (Pn-1);
    const int c = (idx >> (2*lgHn)) & (NF-1);
    const int b = idx >> (2*lgHn + 6);
    const int oy = p >> lgHn, ox = p & (Hn-1);
    const float* src = g_full + (size_t)(b*NF+c)*H*H;
    const float G0 = 0.27406861906119695f;
    const float G1 = 0.72593138093880305f;
    const float u4[4] = {G0, G1, G1, G0};
    float acc = 0.f;
    #pragma unroll
    for (int r = 0; r < 4; ++r) {
        int yy = 2*oy + r - 1;
        if (yy < 0 || yy >= H) continue;
        float rowacc = 0.f;
        #pragma unroll
        for (int cc = 0; cc < 4; ++cc) {
            int xx = 2*ox + cc - 1;
            if (xx < 0 || xx >= H) continue;
            rowacc += u4[cc]*src[(yy<<lgH)+xx];
        }
        acc += u4[r]*rowacc;
    }
    acc *= 0.25f;
    const size_t o = (size_t)(b*NF+c)*Pn + p;
    g_out[o] = acc;
    emb[o]   = acc;
}

// ---------------- tail res_block at 2x2 + spatial mean -> g_hvec ----------------
__global__ void k_tail(const float* __restrict__ w0, const float* __restrict__ b0,
                       const float* __restrict__ w1, const float* __restrict__ b1)
{
    __shared__ float s_w0[NF*NF], s_w1[NF*NF], s_a[NF*4];
    const int o = threadIdx.x, b = blockIdx.x;
    for (int e = o; e < NF*NF; e += 64) {
        int r = e >> 6, i = e & 63;
        s_w0[(r<<6) | ((i + r) & 63)] = w0[e];
        s_w1[(r<<6) | ((i + r) & 63)] = w1[e];
    }
    const float bb0 = b0[o], bb1 = b1[o];
    __syncthreads();
    float v[4];
    #pragma unroll
    for (int py = 0; py < 4; ++py) v[py] = g_out[(size_t)(b*NF+o)*4 + py];
    *(float4*)&s_a[o*4] = make_float4(lrelu(v[0]),lrelu(v[1]),lrelu(v[2]),lrelu(v[3]));
    __syncthreads();
    float t[4] = {bb0,bb0,bb0,bb0};
    #pragma unroll
    for (int i = 0; i < NF; ++i) {
        float w = s_w0[(o<<6) | ((i + o) & 63)];
        float4 a = *(const float4*)&s_a[i*4];
        t[0] += w*a.x; t[1] += w*a.y; t[2] += w*a.z; t[3] += w*a.w;
    }
    __syncthreads();
    *(float4*)&s_a[o*4] = make_float4(lrelu(t[0]),lrelu(t[1]),lrelu(t[2]),lrelu(t[3]));
    __syncthreads();
    float u[4] = {bb1,bb1,bb1,bb1};
    #pragma unroll
    for (int i = 0; i < NF; ++i) {
        float w = s_w1[(o<<6) | ((i + o) & 63)];
        float4 a = *(const float4*)&s_a[i*4];
        u[0] += w*a.x; u[1] += w*a.y; u[2] += w*a.z; u[3] += w*a.w;
    }
    float m = 0.25f*((v[0]+0.1f*u[0]) + (v[1]+0.1f*u[1]) + (v[2]+0.1f*u[2]) + (v[3]+0.1f*u[3]));
    g_hvec[b*NF+o] = m;
}

// ---------------- latent head ----------------
__global__ void __launch_bounds__(512) k_head(
    const float* __restrict__ l1_sw, const float* __restrict__ l1_sb,
    const float* __restrict__ l1_w1, const float* __restrict__ l1_b1,
    const float* __restrict__ l1_w2, const float* __restrict__ l1_b2,
    const float* __restrict__ l2_w1, const float* __restrict__ l2_b1,
    const float* __restrict__ l2_w2, const float* __restrict__ l2_b2,
    const float* __restrict__ lo_w,  const float* __restrict__ lo_b,
    float* __restrict__ lat)
{
    __shared__ float s_h[NF], s_ha[NF];
    __shared__ float s_t[2*LATD];
    __shared__ float s_u[LATD];
    __shared__ float s_hh[LATD];
    const int j = threadIdx.x, b = blockIdx.x;
    if (j < NF) { float h = g_hvec[b*NF+j]; s_h[j] = h; s_ha[j] = lrelu(h); }
    __syncthreads();
    float xs = l1_sb[j];
    for (int i = 0; i < NF; ++i) xs += s_h[i]*l1_sw[i*LATD + j];
    float t0 = l1_b1[j], t1 = l1_b1[j+LATD];
    for (int i = 0; i < NF; ++i) {
        float a = s_ha[i];
        t0 += a*l1_w1[i*2*LATD + j];
        t1 += a*l1_w1[i*2*LATD + j + LATD];
    }
    s_t[j] = lrelu(t0); s_t[j+LATD] = lrelu(t1);
    __syncthreads();
    float v = l1_b2[j];
    for (int i = 0; i < 2*LATD; ++i) v += s_t[i]*l1_w2[(size_t)i*LATD + j];
    float hh = xs + 0.1f*v;
    s_hh[j] = hh; s_u[j] = lrelu(hh);
    __syncthreads();
    float t2 = l2_b1[j];
    for (int i = 0; i < LATD; ++i) t2 += s_u[i]*l2_w1[(size_t)i*LATD + j];
    __syncthreads();
    s_u[j] = lrelu(t2);
    __syncthreads();
    float v2 = l2_b2[j];
    for (int i = 0; i < LATD; ++i) v2 += s_u[i]*l2_w2[(size_t)i*LATD + j];
    float g = s_hh[j] + 0.1f*v2;
    s_t[j] = g;
    __syncthreads();
    float outv = lo_b[j];
    for (int i = 0; i < LATD; ++i) outv += s_t[i]*lo_w[(size_t)i*LATD + j];
    lat[b*LATD + j] = outv;
}

// ---------------- host launcher ----------------
extern "C" void kernel_launch(void* const* d_in, const int* in_sizes, int n_in,
                              void* d_out, int out_size)
{
    const float* x        = (const float*)d_in[0];
    const float* inj      = (const float*)d_in[1];
    const float* leak     = (const float*)d_in[2];
    const float* in_w     = (const float*)d_in[3];
    const float* in_b     = (const float*)d_in[4];
    const float* inrb_w0  = (const float*)d_in[5];
    const float* inrb_b0  = (const float*)d_in[6];
    const float* inrb_w1  = (const float*)d_in[7];
    const float* inrb_b1  = (const float*)d_in[8];
    const float* hyp_w    = (const float*)d_in[9];
    const float* hyp_b    = (const float*)d_in[10];
    const float* outrb_w0 = (const float*)d_in[11];
    const float* outrb_b0 = (const float*)d_in[12];
    const float* outrb_w1 = (const float*)d_in[13];
    const float* outrb_b1 = (const float*)d_in[14];
    const float* l1_sw    = (const float*)d_in[15];
    const float* l1_sb    = (const float*)d_in[16];
    const float* l1_w1    = (const float*)d_in[17];
    const float* l1_b1    = (const float*)d_in[18];
    const float* l1_w2    = (const float*)d_in[19];
    const float* l1_b2    = (const float*)d_in[20];
    const float* l2_w1    = (const float*)d_in[21];
    const float* l2_b1    = (const float*)d_in[22];
    const float* l2_w2    = (const float*)d_in[23];
    const float* l2_b2    = (const float*)d_in[24];
    const float* lo_w     = (const float*)d_in[25];
    const float* lo_b     = (const float*)d_in[26];
    float* out = (float*)d_out;

    float *p_perc, *p_h1, *p_h2, *p_full, *p_out, *p_wAT, *p_wMT, *p_wCDT, *p_bA, *p_bM, *p_bCD, *p_wRB;
    cudaGetSymbolAddress((void**)&p_perc, g_perc);
    cudaGetSymbolAddress((void**)&p_h1,   g_h1);
    cudaGetSymbolAddress((void**)&p_h2,   g_h2);
    cudaGetSymbolAddress((void**)&p_full, g_full);
    cudaGetSymbolAddress((void**)&p_out,  g_out);
    cudaGetSymbolAddress((void**)&p_wAT,  g_wAT);
    cudaGetSymbolAddress((void**)&p_wMT,  g_wMT);
    cudaGetSymbolAddress((void**)&p_wCDT, g_wCDT);
    cudaGetSymbolAddress((void**)&p_bA,   g_bA);
    cudaGetSymbolAddress((void**)&p_bM,   g_bM);
    cudaGetSymbolAddress((void**)&p_bCD,  g_bCD);
    cudaGetSymbolAddress((void**)&p_wRB,  g_wRB);

    float* emb0 = out + (size_t)BB*LATD;   // lat occupies [0, 4096)

    // input path: y = conv1x1(x) -> g_full ; resblock via shared-weight GEMMs
    k_inconv<<<8192, 256>>>(x, in_w, in_b);
    k_trw<<<32, 256>>>(inrb_w0, inrb_w1);
    k_hyper<<<(PT + 127)/128, 128>>>(inj, hyp_w, hyp_b);
    k_tr<<<dim3((61760 + 255)/256, BB), 256>>>();

    // h1 = lrelu( lrelu(y) @ w0 + b0 )
    k_gemm<256,64,0,true><<<dim3(P0/256, BB), 256>>>(
        p_full, NF, (long long)NF*P0, nullptr, 0, 0,
        p_wRB, NF, 0, inrb_b0, 0,
        p_h1, (long long)NF*P0, nullptr, nullptr, nullptr, P0);
    // out = y + 0.1*( h1 @ w1 + b1 )  -> g_out and emb0
    k_gemm<256,64,2,false><<<dim3(P0/256, BB), 256>>>(
        p_h1, NF, (long long)NF*P0, nullptr, 0, 0,
        p_wRB + NF*NF, NF, 0, inrb_b1, 0,
        p_out, (long long)NF*P0, emb0, p_full, nullptr, P0);

    size_t off = (size_t)BB*LATD + (size_t)BB*NF*P0;
    int H = 128, lgH = 7;
    for (int it = 0; it < 6; ++it) {
        int P = H*H;
        k_sobel4<<<(BB*NF*(P/4) + 255)/256, 256>>>(H, lgH);
        k_gemm<128,128,0,false><<<dim3((P + 127)/128, BB), 256>>>(
            p_perc, FIN, (long long)FIN*P, nullptr, 0, 0,
            p_wAT, FH, (long long)FIN*FH, p_bA, FH,
            p_h1, (long long)FH*P, nullptr, nullptr, nullptr, P);
        k_gemm<128,128,0,false><<<dim3((P + 127)/128, BB), 256>>>(
            p_h1, FH, (long long)FH*P, nullptr, 0, 0,
            p_wMT, FH, (long long)FH*FH, p_bM, FH,
            p_h2, (long long)FH*P, nullptr, nullptr, nullptr, P);
        k_gemm<256,64,1,false><<<dim3((P + 255)/256, BB), 256>>>(
            p_h2, FH, (long long)FH*P, p_perc, FIN, (long long)FIN*P,
            p_wCDT, NF, (long long)320*NF, p_bCD, NF,
            p_full, (long long)NF*P, nullptr, p_out, leak, P);
        int Hn = H/2, Pn = Hn*Hn;
        k_down<<<(BB*NF*Pn + 255)/256, 256>>>(H, lgH, out + off);
        off += (size_t)BB*NF*Pn;
        H = Hn; lgH -= 1;
    }
    k_tail<<<BB, 64>>>(outrb_w0, outrb_b0, outrb_w1, outrb_b1);
    k_head<<<BB, 512>>>(l1_sw, l1_sb, l1_w1, l1_b1, l1_w2, l1_b2,
                        l2_w1, l2_b1, l2_w2, l2_b2, lo_w, lo_b, out);
}